// round 11
// baseline (speedup 1.0000x reference)
#include <cuda_runtime.h>
#include <cuda_fp16.h>
#include <math.h>
#include <stdint.h>

// ---------------------------------------------------------------------------
// SelfAttention — round 10: R8 base (fp16 mma.sync, CTA 128x128x64, 4 warps,
// 64x64 warp tiles, frag ping-pong, 3-stage cp.async, 2 CTAs/SM) plus:
//  * cp.async for tile t+2 interleaved across MMA slabs (lower MLP_p1)
//  * GEMM1 epilogue fuses the k0^T / v^T transposes (kernels deleted)
// kv = X @ Wqk^T ; s = K0^T V^T * c ; a = softmax(s) ; q = a @ V ;
// out = perm(q) @ Wd^T + b.     B=4, T=2048, D=2048, H=16.
// ---------------------------------------------------------------------------

#define BM 128
#define BN 128
#define BK 64                        // halves
#define STAGES 3
#define A_BYTES 16384                // 128 rows * 128B
#define B_BYTES 16384
#define STAGE_BYTES (A_BYTES + B_BYTES)
#define SMEM_TOTAL (STAGES * STAGE_BYTES)
#define NTHREADS 128

__device__ __half g_xh [4L * 2048 * 2048];
__device__ __half g_wqk[4096L * 2048];
__device__ __half g_wd [2048L * 2048];
__device__ __half g_kv [4L * 2048 * 4096];
__device__ __half g_k0t[4L * 2048 * 2048];
__device__ __half g_vt [4L * 2048 * 2048];
__device__ __half g_s  [4L * 2048 * 2048];
__device__ __half g_q  [4L * 2048 * 2048];

static __device__ __forceinline__ uint32_t smem_u32(const void* p) {
    uint32_t a;
    asm("{ .reg .u64 t; cvta.to.shared.u64 t, %1; cvt.u32.u64 %0, t; }"
        : "=r"(a) : "l"(p));
    return a;
}
static __device__ __forceinline__ void cp16(uint32_t dst, const void* src) {
    asm volatile("cp.async.cg.shared.global [%0], [%1], 16;\n" :: "r"(dst), "l"(src));
}
static __device__ __forceinline__ void cp_commit() {
    asm volatile("cp.async.commit_group;\n");
}
template<int N> static __device__ __forceinline__ void cp_wait() {
    asm volatile("cp.async.wait_group %0;\n" :: "n"(N));
}
static __device__ __forceinline__ void ldsm4(uint32_t& r0, uint32_t& r1,
                                             uint32_t& r2, uint32_t& r3,
                                             uint32_t addr) {
    asm volatile("ldmatrix.sync.aligned.m8n8.x4.shared.b16 {%0,%1,%2,%3}, [%4];"
                 : "=r"(r0), "=r"(r1), "=r"(r2), "=r"(r3) : "r"(addr));
}
static __device__ __forceinline__ void mma_f16(float c[4], const uint32_t a[4],
                                               const uint32_t b[2]) {
    asm volatile(
        "mma.sync.aligned.m16n8k16.row.col.f32.f16.f16.f32 "
        "{%0,%1,%2,%3}, {%4,%5,%6,%7}, {%8,%9}, {%0,%1,%2,%3};\n"
        : "+f"(c[0]), "+f"(c[1]), "+f"(c[2]), "+f"(c[3])
        : "r"(a[0]), "r"(a[1]), "r"(a[2]), "r"(a[3]), "r"(b[0]), "r"(b[1]));
}

// smem tile rows of 64 halves = 128B = 8 chunks of 16B; chunk ^= row&7.
static __device__ __forceinline__ uint32_t tile_addr(uint32_t base, int row, int k) {
    return base + (uint32_t)(row * 128 + ((((k >> 3) ^ (row & 7))) << 4)
                             + ((k & 7) << 1));
}

// C = alpha * A·B^T (+bias). A:[M,K] K-major half, B:[N,K] K-major half.
// TROUT: additionally scatter-transpose the product into k0t/vt (GEMM1 only).
template<bool OUTF32, bool BIAS, bool PERMOUT, bool TROUT>
__global__ __launch_bounds__(NTHREADS, 2)
void gemm_h(const __half* __restrict__ A, const __half* __restrict__ B,
            void* __restrict__ Cv, const float* __restrict__ bias,
            __half* __restrict__ k0t, __half* __restrict__ vt,
            int K, long sA, long sB, long ldc,
            long bA, long bB, long bC, float alpha)
{
    extern __shared__ __half smem[];
    const uint32_t sbase = smem_u32(smem);

    A += (long)blockIdx.z * bA;
    B += (long)blockIdx.z * bB;

    const int tid  = threadIdx.x;
    const int warp = tid >> 5;
    const int lane = tid & 31;
    const int wm   = warp >> 1;          // 0..1  (64-row slice)
    const int wn   = warp & 1;           // 0..1  (64-col slice)
    const int g    = lane >> 2;          // 0..7
    const int tig  = lane & 3;           // 0..3
    const long rowBase = (long)blockIdx.y * BM;
    const long colBase = (long)blockIdx.x * BN;

    // ldmatrix lane-derived fragment coords
    const int lblk = lane >> 3;
    const int frag_row = ((lblk & 1) << 3) + (lane & 7);
    const int frag_kc  = (lblk >> 1) << 3;

    float acc[4][8][4];
#pragma unroll
    for (int i = 0; i < 4; ++i)
#pragma unroll
        for (int j = 0; j < 8; ++j)
#pragma unroll
            for (int c = 0; c < 4; ++c) acc[i][j][c] = 0.f;

    // issue 4 of the 16 cp.async chunks for tile t (part 0..3)
    auto issuePart = [&](int t, int part) {
        const int st = t % STAGES;
        const uint32_t aB = sbase + (uint32_t)st * STAGE_BYTES;
        const uint32_t bB2 = aB + A_BYTES;
        const int k0 = t * BK;
#pragma unroll
        for (int r = 0; r < 2; ++r) {
            int idx = tid + (part * 2 + r) * 128;
            int row = idx >> 3, c = idx & 7;
            cp16(aB + (uint32_t)(row * 128 + ((c ^ (row & 7)) << 4)),
                 A + (rowBase + row) * sA + (k0 + c * 8));
        }
#pragma unroll
        for (int r = 0; r < 2; ++r) {
            int idx = tid + (part * 2 + r) * 128;
            int row = idx >> 3, c = idx & 7;
            cp16(bB2 + (uint32_t)(row * 128 + ((c ^ (row & 7)) << 4)),
                 B + (colBase + row) * sB + (k0 + c * 8));
        }
    };
    auto issueTile = [&](int t) {
#pragma unroll
        for (int p = 0; p < 4; ++p) issuePart(t, p);
    };

    auto loadFragsA = [&](uint32_t aB, int ks, uint32_t a[4][4]) {
#pragma unroll
        for (int i = 0; i < 4; ++i) {
            int row = wm * 64 + i * 16 + frag_row;
            ldsm4(a[i][0], a[i][1], a[i][2], a[i][3],
                  tile_addr(aB, row, ks + frag_kc));
        }
    };
    auto loadFragsB = [&](uint32_t bB2, int ks, uint32_t b[8][2]) {
#pragma unroll
        for (int j2 = 0; j2 < 4; ++j2) {
            int nrow = wn * 64 + j2 * 16 + frag_row;
            uint32_t q0, q1, q2, q3;
            ldsm4(q0, q1, q2, q3, tile_addr(bB2, nrow, ks + frag_kc));
            b[2 * j2][0] = q0; b[2 * j2 + 1][0] = q1;
            b[2 * j2][1] = q2; b[2 * j2 + 1][1] = q3;
        }
    };

    // compute tile in `stage`; interleave cp.async parts of tile tNext
    auto compute = [&](int stage, int tNext, bool doNext) {
        const uint32_t aB = sbase + (uint32_t)stage * STAGE_BYTES;
        const uint32_t bB2 = aB + A_BYTES;
        uint32_t afr[2][4][4], bfr[2][8][2];
        loadFragsA(aB, 0, afr[0]);
        loadFragsB(bB2, 0, bfr[0]);
#pragma unroll
        for (int slab = 0; slab < 4; ++slab) {
            const int cur = slab & 1, nxt = cur ^ 1;
            if (slab < 3) {
                loadFragsA(aB, (slab + 1) * 16, afr[nxt]);
                loadFragsB(bB2, (slab + 1) * 16, bfr[nxt]);
            }
            if (doNext) issuePart(tNext, slab);
#pragma unroll
            for (int i = 0; i < 4; ++i)
#pragma unroll
                for (int j = 0; j < 8; ++j)
                    mma_f16(acc[i][j], afr[cur][i], bfr[cur][j]);
        }
    };

    const int nt = K / BK;
    issueTile(0); cp_commit();
    issueTile(1); cp_commit();

    for (int t = 0; t < nt; ++t) {
        cp_wait<1>();
        __syncthreads();
        compute(t % STAGES, t + 2, t + 2 < nt);
        cp_commit();                       // one group per iter (maybe empty)
    }

    // ---- epilogue ----
#pragma unroll
    for (int i = 0; i < 4; ++i) {
#pragma unroll
        for (int hh = 0; hh < 2; ++hh) {
            long rloc = rowBase + wm * 64 + i * 16 + g + hh * 8;
            long orow;
            if (PERMOUT) {
                int ii = (int)rloc;          // rowBase spans [0,2048)
                int bb = blockIdx.z;
                orow = (long)((ii & 127) >> 5) * 2048
                     + (long)(((ii & 31) << 6) | (bb << 4) | (ii >> 7));
            } else {
                orow = rloc;
            }
            // fused-transpose base (TROUT: rloc in [0,8192))
            long tb = 0;
            if (TROUT)
                tb = (rloc >> 11) * (2048L * 2048) + (rloc & 2047);
#pragma unroll
            for (int j = 0; j < 8; ++j) {
                long col = colBase + wn * 64 + j * 8 + tig * 2;
                float v0 = acc[i][j][hh * 2]     * alpha;
                float v1 = acc[i][j][hh * 2 + 1] * alpha;
                if (OUTF32) {
                    float* C = (float*)Cv + (long)blockIdx.z * bC;
                    if (BIAS) {
                        const float2 bv = *(const float2*)(bias + col);
                        v0 += bv.x; v1 += bv.y;
                    }
                    *(float2*)(C + orow * ldc + col) = make_float2(v0, v1);
                } else {
                    __half* C = (__half*)Cv + (long)blockIdx.z * bC;
                    __half2 hv = __floats2half2_rn(v0, v1);
                    *(__half2*)(C + orow * ldc + col) = hv;
                    if (TROUT) {
                        __half* T = (col < 2048)
                                  ? (k0t + tb + col * 2048L)
                                  : (vt  + tb + (col - 2048) * 2048L);
                        T[0]    = __low2half(hv);
                        T[2048] = __high2half(hv);
                    }
                }
            }
        }
    }
}

// float -> half conversion (4 elems/thread)
__global__ __launch_bounds__(256)
void to_half(const float* __restrict__ in, __half* __restrict__ out, long n4)
{
    long i = (long)blockIdx.x * blockDim.x + threadIdx.x;
    long stride = (long)gridDim.x * blockDim.x;
    for (; i < n4; i += stride) {
        float4 v = ((const float4*)in)[i];
        ((__half2*)out)[2 * i]     = __floats2half2_rn(v.x, v.y);
        ((__half2*)out)[2 * i + 1] = __floats2half2_rn(v.z, v.w);
    }
}

// softmax over half rows of 2048 (fp32 math), in place.
__global__ __launch_bounds__(256)
void softmax2048h(__half* __restrict__ S)
{
    const long row = blockIdx.x;
    __half* p = S + row * 2048;
    const int tid = threadIdx.x, lane = tid & 31, wid = tid >> 5;

    float v[8];
    float m = -1e30f;
#pragma unroll
    for (int j = 0; j < 8; ++j) {
        v[j] = __half2float(p[tid + j * 256]);
        m = fmaxf(m, v[j]);
    }
#pragma unroll
    for (int o = 16; o > 0; o >>= 1)
        m = fmaxf(m, __shfl_xor_sync(0xFFFFFFFFu, m, o));
    __shared__ float red[8];
    if (lane == 0) red[wid] = m;
    __syncthreads();
    float mm = red[0];
#pragma unroll
    for (int w = 1; w < 8; ++w) mm = fmaxf(mm, red[w]);
    __syncthreads();
    float sum = 0.f;
#pragma unroll
    for (int j = 0; j < 8; ++j) { v[j] = expf(v[j] - mm); sum += v[j]; }
#pragma unroll
    for (int o = 16; o > 0; o >>= 1)
        sum += __shfl_xor_sync(0xFFFFFFFFu, sum, o);
    if (lane == 0) red[wid] = sum;
    __syncthreads();
    float tot = 0.f;
#pragma unroll
    for (int w = 0; w < 8; ++w) tot += red[w];
    const float inv = 1.f / tot;
#pragma unroll
    for (int j = 0; j < 8; ++j)
        p[tid + j * 256] = __float2half_rn(v[j] * inv);
}

extern "C" void kernel_launch(void* const* d_in, const int* in_sizes, int n_in,
                              void* d_out, int out_size)
{
    const float* x       = (const float*)d_in[0];
    const float* w_qk    = (const float*)d_in[1];
    const float* w_dense = (const float*)d_in[2];
    const float* b_dense = (const float*)d_in[3];
    float* out = (float*)d_out;

    __half *xh, *wqkh, *wdh, *kv, *k0t, *vt, *s, *q;
    cudaGetSymbolAddress((void**)&xh,   g_xh);
    cudaGetSymbolAddress((void**)&wqkh, g_wqk);
    cudaGetSymbolAddress((void**)&wdh,  g_wd);
    cudaGetSymbolAddress((void**)&kv,   g_kv);
    cudaGetSymbolAddress((void**)&k0t,  g_k0t);
    cudaGetSymbolAddress((void**)&vt,   g_vt);
    cudaGetSymbolAddress((void**)&s,    g_s);
    cudaGetSymbolAddress((void**)&q,    g_q);

    static int attr_done = 0;
    if (!attr_done) {
        cudaFuncSetAttribute(gemm_h<false, false, false, true>,
                             cudaFuncAttributeMaxDynamicSharedMemorySize, SMEM_TOTAL);
        cudaFuncSetAttribute(gemm_h<false, false, false, false>,
                             cudaFuncAttributeMaxDynamicSharedMemorySize, SMEM_TOTAL);
        cudaFuncSetAttribute(gemm_h<false, false, true,  false>,
                             cudaFuncAttributeMaxDynamicSharedMemorySize, SMEM_TOTAL);
        cudaFuncSetAttribute(gemm_h<true,  true,  false, false>,
                             cudaFuncAttributeMaxDynamicSharedMemorySize, SMEM_TOTAL);
        attr_done = 1;
    }

    const float scale = (float)(1.0 / sqrt((double)2048 * 2047 / 2.0));

    // 0) convert inputs to half
    to_half<<<1024, 256>>>(x,       xh,   (4L * 2048 * 2048) / 4);
    to_half<<<512,  256>>>(w_qk,    wqkh, (4096L * 2048) / 4);
    to_half<<<512,  256>>>(w_dense, wdh,  (2048L * 2048) / 4);

    // 1) kv = X @ Wqk^T : M=8192, N=4096 (half out) + fused k0t/vt transposes
    gemm_h<false, false, false, true><<<dim3(4096 / BN, 8192 / BM, 1), NTHREADS, SMEM_TOTAL>>>(
        xh, wqkh, kv, nullptr, k0t, vt,
        2048, 2048, 2048, 4096, 0, 0, 0, 1.f);

    // 2) s[b,i,j] = scale * sum_m k0t[b,i,m] * v[b,j,m]   (half out)
    gemm_h<false, false, false, false><<<dim3(2048 / BN, 2048 / BM, 4), NTHREADS, SMEM_TOTAL>>>(
        k0t, kv + 2048, s, nullptr, nullptr, nullptr,
        2048, 2048, 4096, 2048,
        2048L * 2048, 2048L * 4096, 2048L * 2048, scale);

    // 3) a = softmax(s) in-place (half)
    softmax2048h<<<8192, 256>>>(s);

    // 4) qp[perm(b,i), d] = sum_t a[b,i,t] * vt[b,d,t]   (half out, perm rows)
    gemm_h<false, false, true, false><<<dim3(2048 / BN, 2048 / BM, 4), NTHREADS, SMEM_TOTAL>>>(
        s, vt, q, nullptr, nullptr, nullptr,
        2048, 2048, 2048, 2048,
        2048L * 2048, 2048L * 2048, 0, 1.f);

    // 5) out = qp @ Wd^T + b : M=8192, N=2048  (float out + bias)
    gemm_h<true, true, false, false><<<dim3(2048 / BN, 8192 / BM, 1), NTHREADS, SMEM_TOTAL>>>(
        q, wdh, out, b_dense, nullptr, nullptr,
        2048, 2048, 2048, 2048, 0, 0, 0, 1.f);
}

// round 12
// speedup vs baseline: 1.2547x; 1.2547x over previous
#include <cuda_runtime.h>
#include <cuda_fp16.h>
#include <math.h>
#include <stdint.h>

// ---------------------------------------------------------------------------
// SelfAttention — round 11: R8 base (fp16 mma.sync, CTA 128x128x64, 4 warps,
// 64x64 warp tiles, 3-stage cp.async, 2 CTAs/SM) with:
//  * warp-self-sufficient cp.async (each warp copies the rows it ldsm's)
//  * cross-tile slab-0 fragment prefetch (kills the post-barrier bubble)
//  * exactly one __syncthreads / commit / wait per mainloop iteration
// kv = X @ Wqk^T ; s = K0^T V^T * c ; a = softmax(s) ; q = a @ V ;
// out = perm(q) @ Wd^T + b.     B=4, T=2048, D=2048, H=16.
// ---------------------------------------------------------------------------

#define BM 128
#define BN 128
#define BK 64                        // halves
#define STAGES 3
#define A_BYTES 16384                // 128 rows * 128B
#define B_BYTES 16384
#define STAGE_BYTES (A_BYTES + B_BYTES)
#define SMEM_TOTAL (STAGES * STAGE_BYTES)
#define NTHREADS 128

__device__ __half g_xh [4L * 2048 * 2048];
__device__ __half g_wqk[4096L * 2048];
__device__ __half g_wd [2048L * 2048];
__device__ __half g_kv [4L * 2048 * 4096];
__device__ __half g_k0t[4L * 2048 * 2048];
__device__ __half g_vt [4L * 2048 * 2048];
__device__ __half g_s  [4L * 2048 * 2048];
__device__ __half g_q  [4L * 2048 * 2048];

static __device__ __forceinline__ uint32_t smem_u32(const void* p) {
    uint32_t a;
    asm("{ .reg .u64 t; cvta.to.shared.u64 t, %1; cvt.u32.u64 %0, t; }"
        : "=r"(a) : "l"(p));
    return a;
}
static __device__ __forceinline__ void cp16(uint32_t dst, const void* src) {
    asm volatile("cp.async.cg.shared.global [%0], [%1], 16;\n" :: "r"(dst), "l"(src));
}
static __device__ __forceinline__ void cp_commit() {
    asm volatile("cp.async.commit_group;\n");
}
template<int N> static __device__ __forceinline__ void cp_wait() {
    asm volatile("cp.async.wait_group %0;\n" :: "n"(N));
}
static __device__ __forceinline__ void ldsm4(uint32_t& r0, uint32_t& r1,
                                             uint32_t& r2, uint32_t& r3,
                                             uint32_t addr) {
    asm volatile("ldmatrix.sync.aligned.m8n8.x4.shared.b16 {%0,%1,%2,%3}, [%4];"
                 : "=r"(r0), "=r"(r1), "=r"(r2), "=r"(r3) : "r"(addr));
}
static __device__ __forceinline__ void mma_f16(float c[4], const uint32_t a[4],
                                               const uint32_t b[2]) {
    asm volatile(
        "mma.sync.aligned.m16n8k16.row.col.f32.f16.f16.f32 "
        "{%0,%1,%2,%3}, {%4,%5,%6,%7}, {%8,%9}, {%0,%1,%2,%3};\n"
        : "+f"(c[0]), "+f"(c[1]), "+f"(c[2]), "+f"(c[3])
        : "r"(a[0]), "r"(a[1]), "r"(a[2]), "r"(a[3]), "r"(b[0]), "r"(b[1]));
}

// smem tile rows of 64 halves = 128B = 8 chunks of 16B; chunk ^= row&7.
static __device__ __forceinline__ uint32_t tile_addr(uint32_t base, int row, int k) {
    return base + (uint32_t)(row * 128 + ((((k >> 3) ^ (row & 7))) << 4)
                             + ((k & 7) << 1));
}

// C = alpha * A·B^T (+bias). A:[M,K] K-major half, B:[N,K] K-major half.
template<bool OUTF32, bool BIAS, bool PERMOUT>
__global__ __launch_bounds__(NTHREADS, 2)
void gemm_h(const __half* __restrict__ A, const __half* __restrict__ B,
            void* __restrict__ Cv, const float* __restrict__ bias,
            int K, long sA, long sB, long ldc,
            long bA, long bB, long bC, float alpha)
{
    extern __shared__ __half smem[];
    const uint32_t sbase = smem_u32(smem);

    A += (long)blockIdx.z * bA;
    B += (long)blockIdx.z * bB;

    const int tid  = threadIdx.x;
    const int warp = tid >> 5;
    const int lane = tid & 31;
    const int wm   = warp >> 1;          // 0..1  (64-row A slice)
    const int wn   = warp & 1;           // 0..1  (64-row B slice)
    const int g    = lane >> 2;
    const int tig  = lane & 3;
    const long rowBase = (long)blockIdx.y * BM;
    const long colBase = (long)blockIdx.x * BN;

    // ldmatrix lane-derived fragment coords
    const int lblk = lane >> 3;
    const int frag_row = ((lblk & 1) << 3) + (lane & 7);
    const int frag_kc  = (lblk >> 1) << 3;

    float acc[4][8][4];
#pragma unroll
    for (int i = 0; i < 4; ++i)
#pragma unroll
        for (int j = 0; j < 8; ++j)
#pragma unroll
            for (int c = 0; c < 4; ++c) acc[i][j][c] = 0.f;

    // warp-self-sufficient tile load: this warp copies its A half (rows
    // wm*64..+64) and B half (rows wn*64..+64). Partner warps duplicate the
    // same rows with identical data (benign).
    auto issueW = [&](int t) {
        const int st = t % STAGES;
        const uint32_t aB = sbase + (uint32_t)st * STAGE_BYTES;
        const uint32_t bB2 = aB + A_BYTES;
        const int k0 = t * BK;
#pragma unroll
        for (int i = 0; i < 16; ++i) {
            int idx = lane + i * 32;             // 0..511
            int row = wm * 64 + (idx >> 3), c = idx & 7;
            cp16(aB + (uint32_t)(row * 128 + ((c ^ (row & 7)) << 4)),
                 A + (rowBase + row) * sA + (k0 + c * 8));
        }
#pragma unroll
        for (int i = 0; i < 16; ++i) {
            int idx = lane + i * 32;
            int row = wn * 64 + (idx >> 3), c = idx & 7;
            cp16(bB2 + (uint32_t)(row * 128 + ((c ^ (row & 7)) << 4)),
                 B + (colBase + row) * sB + (k0 + c * 8));
        }
    };

    auto loadFragsA = [&](uint32_t aB, int ks, uint32_t a[4][4]) {
#pragma unroll
        for (int i = 0; i < 4; ++i) {
            int row = wm * 64 + i * 16 + frag_row;
            ldsm4(a[i][0], a[i][1], a[i][2], a[i][3],
                  tile_addr(aB, row, ks + frag_kc));
        }
    };
    auto loadFragsB = [&](uint32_t bB2, int ks, uint32_t b[8][2]) {
#pragma unroll
        for (int j2 = 0; j2 < 4; ++j2) {
            int nrow = wn * 64 + j2 * 16 + frag_row;
            uint32_t q0, q1, q2, q3;
            ldsm4(q0, q1, q2, q3, tile_addr(bB2, nrow, ks + frag_kc));
            b[2 * j2][0] = q0; b[2 * j2 + 1][0] = q1;
            b[2 * j2][1] = q2; b[2 * j2 + 1][1] = q3;
        }
    };

    uint32_t afr[2][4][4], bfr[2][8][2];
    const int nt = K / BK;

    issueW(0); cp_commit();
    issueW(1); cp_commit();
    cp_wait<1>();                         // own tile-0 copies done
    {
        const uint32_t aB = sbase;
        loadFragsA(aB, 0, afr[0]);
        loadFragsB(aB + A_BYTES, 0, bfr[0]);
    }

    int cur = 0;
    for (int t = 0; t < nt; ++t) {
        __syncthreads();                  // stage (t+2)%3 free of readers
        if (t + 2 < nt) issueW(t + 2);
        cp_commit();                      // one group per iter (maybe empty)
        const uint32_t aB = sbase + (uint32_t)(t % STAGES) * STAGE_BYTES;
        const uint32_t bB2 = aB + A_BYTES;
#pragma unroll
        for (int slab = 0; slab < 4; ++slab) {
            const int nxt = cur ^ 1;
            if (slab < 3) {
                loadFragsA(aB, (slab + 1) * 16, afr[nxt]);
                loadFragsB(bB2, (slab + 1) * 16, bfr[nxt]);
            } else {
                cp_wait<1>();             // own tile-(t+1) copies done
                if (t + 1 < nt) {
                    const uint32_t aBn =
                        sbase + (uint32_t)((t + 1) % STAGES) * STAGE_BYTES;
                    loadFragsA(aBn, 0, afr[nxt]);
                    loadFragsB(aBn + A_BYTES, 0, bfr[nxt]);
                }
            }
#pragma unroll
            for (int i = 0; i < 4; ++i)
#pragma unroll
                for (int j = 0; j < 8; ++j)
                    mma_f16(acc[i][j], afr[cur][i], bfr[cur][j]);
            cur = nxt;
        }
    }

    // ---- epilogue ----
#pragma unroll
    for (int i = 0; i < 4; ++i) {
#pragma unroll
        for (int hh = 0; hh < 2; ++hh) {
            long rloc = rowBase + wm * 64 + i * 16 + g + hh * 8;
            long orow;
            if (PERMOUT) {
                int ii = (int)rloc;          // rowBase spans [0,2048)
                int bb = blockIdx.z;
                orow = (long)((ii & 127) >> 5) * 2048
                     + (long)(((ii & 31) << 6) | (bb << 4) | (ii >> 7));
            } else {
                orow = rloc;
            }
#pragma unroll
            for (int j = 0; j < 8; ++j) {
                long col = colBase + wn * 64 + j * 8 + tig * 2;
                float v0 = acc[i][j][hh * 2]     * alpha;
                float v1 = acc[i][j][hh * 2 + 1] * alpha;
                if (OUTF32) {
                    float* C = (float*)Cv + (long)blockIdx.z * bC;
                    if (BIAS) {
                        const float2 bv = *(const float2*)(bias + col);
                        v0 += bv.x; v1 += bv.y;
                    }
                    *(float2*)(C + orow * ldc + col) = make_float2(v0, v1);
                } else {
                    __half* C = (__half*)Cv + (long)blockIdx.z * bC;
                    *(__half2*)(C + orow * ldc + col) = __floats2half2_rn(v0, v1);
                }
            }
        }
    }
}

// float -> half conversion (4 elems/thread)
__global__ __launch_bounds__(256)
void to_half(const float* __restrict__ in, __half* __restrict__ out, long n4)
{
    long i = (long)blockIdx.x * blockDim.x + threadIdx.x;
    long stride = (long)gridDim.x * blockDim.x;
    for (; i < n4; i += stride) {
        float4 v = ((const float4*)in)[i];
        ((__half2*)out)[2 * i]     = __floats2half2_rn(v.x, v.y);
        ((__half2*)out)[2 * i + 1] = __floats2half2_rn(v.z, v.w);
    }
}

// half 32x32 transpose: dst[b][x][y] = src[b][y][colOff + x]
__global__ __launch_bounds__(256)
void transpose_h(const __half* __restrict__ src, __half* __restrict__ dst,
                 long srcStride, long colOff, long srcBatch, long dstBatch)
{
    __shared__ __half tile[32][33];
    const long sb = (long)blockIdx.z * srcBatch;
    const long db = (long)blockIdx.z * dstBatch;
    const int x0 = blockIdx.x * 32, y0 = blockIdx.y * 32;
    const int tx = threadIdx.x, ty = threadIdx.y;
#pragma unroll
    for (int j = 0; j < 4; ++j)
        tile[ty + j * 8][tx] =
            src[sb + (long)(y0 + ty + j * 8) * srcStride + colOff + x0 + tx];
    __syncthreads();
#pragma unroll
    for (int j = 0; j < 4; ++j)
        dst[db + (long)(x0 + ty + j * 8) * 2048 + y0 + tx] = tile[tx][ty + j * 8];
}

// softmax over half rows of 2048 (fp32 math), in place.
__global__ __launch_bounds__(256)
void softmax2048h(__half* __restrict__ S)
{
    const long row = blockIdx.x;
    __half* p = S + row * 2048;
    const int tid = threadIdx.x, lane = tid & 31, wid = tid >> 5;

    float v[8];
    float m = -1e30f;
#pragma unroll
    for (int j = 0; j < 8; ++j) {
        v[j] = __half2float(p[tid + j * 256]);
        m = fmaxf(m, v[j]);
    }
#pragma unroll
    for (int o = 16; o > 0; o >>= 1)
        m = fmaxf(m, __shfl_xor_sync(0xFFFFFFFFu, m, o));
    __shared__ float red[8];
    if (lane == 0) red[wid] = m;
    __syncthreads();
    float mm = red[0];
#pragma unroll
    for (int w = 1; w < 8; ++w) mm = fmaxf(mm, red[w]);
    __syncthreads();
    float sum = 0.f;
#pragma unroll
    for (int j = 0; j < 8; ++j) { v[j] = expf(v[j] - mm); sum += v[j]; }
#pragma unroll
    for (int o = 16; o > 0; o >>= 1)
        sum += __shfl_xor_sync(0xFFFFFFFFu, sum, o);
    if (lane == 0) red[wid] = sum;
    __syncthreads();
    float tot = 0.f;
#pragma unroll
    for (int w = 0; w < 8; ++w) tot += red[w];
    const float inv = 1.f / tot;
#pragma unroll
    for (int j = 0; j < 8; ++j)
        p[tid + j * 256] = __float2half_rn(v[j] * inv);
}

extern "C" void kernel_launch(void* const* d_in, const int* in_sizes, int n_in,
                              void* d_out, int out_size)
{
    const float* x       = (const float*)d_in[0];
    const float* w_qk    = (const float*)d_in[1];
    const float* w_dense = (const float*)d_in[2];
    const float* b_dense = (const float*)d_in[3];
    float* out = (float*)d_out;

    __half *xh, *wqkh, *wdh, *kv, *k0t, *vt, *s, *q;
    cudaGetSymbolAddress((void**)&xh,   g_xh);
    cudaGetSymbolAddress((void**)&wqkh, g_wqk);
    cudaGetSymbolAddress((void**)&wdh,  g_wd);
    cudaGetSymbolAddress((void**)&kv,   g_kv);
    cudaGetSymbolAddress((void**)&k0t,  g_k0t);
    cudaGetSymbolAddress((void**)&vt,   g_vt);
    cudaGetSymbolAddress((void**)&s,    g_s);
    cudaGetSymbolAddress((void**)&q,    g_q);

    static int attr_done = 0;
    if (!attr_done) {
        cudaFuncSetAttribute(gemm_h<false, false, false>,
                             cudaFuncAttributeMaxDynamicSharedMemorySize, SMEM_TOTAL);
        cudaFuncSetAttribute(gemm_h<false, false, true>,
                             cudaFuncAttributeMaxDynamicSharedMemorySize, SMEM_TOTAL);
        cudaFuncSetAttribute(gemm_h<true,  true,  false>,
                             cudaFuncAttributeMaxDynamicSharedMemorySize, SMEM_TOTAL);
        attr_done = 1;
    }

    const float scale = (float)(1.0 / sqrt((double)2048 * 2047 / 2.0));

    // 0) convert inputs to half
    to_half<<<1024, 256>>>(x,       xh,   (4L * 2048 * 2048) / 4);
    to_half<<<512,  256>>>(w_qk,    wqkh, (4096L * 2048) / 4);
    to_half<<<512,  256>>>(w_dense, wdh,  (2048L * 2048) / 4);

    // 1) kv = X @ Wqk^T : M=8192, N=4096  (half out)
    gemm_h<false, false, false><<<dim3(4096 / BN, 8192 / BM, 1), NTHREADS, SMEM_TOTAL>>>(
        xh, wqkh, kv, nullptr, 2048, 2048, 2048, 4096, 0, 0, 0, 1.f);

    // 1b) k0t[b,i,m] = kv[b,m,i];  vt[b,d,t] = kv[b,t,2048+d]
    transpose_h<<<dim3(64, 64, 4), dim3(32, 8)>>>(kv, k0t, 4096, 0,
                                                  2048L * 4096, 2048L * 2048);
    transpose_h<<<dim3(64, 64, 4), dim3(32, 8)>>>(kv, vt, 4096, 2048,
                                                  2048L * 4096, 2048L * 2048);

    // 2) s[b,i,j] = scale * sum_m k0t[b,i,m] * v[b,j,m]   (half out)
    gemm_h<false, false, false><<<dim3(2048 / BN, 2048 / BM, 4), NTHREADS, SMEM_TOTAL>>>(
        k0t, kv + 2048, s, nullptr, 2048, 2048, 4096, 2048,
        2048L * 2048, 2048L * 4096, 2048L * 2048, scale);

    // 3) a = softmax(s) in-place (half)
    softmax2048h<<<8192, 256>>>(s);

    // 4) qp[perm(b,i), d] = sum_t a[b,i,t] * vt[b,d,t]   (half out, perm rows)
    gemm_h<false, false, true><<<dim3(2048 / BN, 2048 / BM, 4), NTHREADS, SMEM_TOTAL>>>(
        s, vt, q, nullptr, 2048, 2048, 2048, 2048,
        2048L * 2048, 2048L * 2048, 0, 1.f);

    // 5) out = qp @ Wd^T + b : M=8192, N=2048  (float out + bias)
    gemm_h<true, true, false><<<dim3(2048 / BN, 8192 / BM, 1), NTHREADS, SMEM_TOTAL>>>(
        q, wdh, out, b_dense, 2048, 2048, 2048, 2048, 0, 0, 0, 1.f);
}

// round 13
// speedup vs baseline: 1.9603x; 1.5624x over previous
#include <cuda_runtime.h>
#include <cuda_fp16.h>
#include <math.h>
#include <stdint.h>

// ---------------------------------------------------------------------------
// SelfAttention — round 12: R8 config (fp16 mma.sync, CTA 128x128x64, 4 warps,
// 64x64 warp tiles, frag ping-pong, 3-stage cp.async, 2 CTAs/SM) with the
// mainloop ROTATED: barrier+issue+next-tile-slab0-prefetch moved before the
// last slab's MMAs, so post-barrier LDSM latency hides under 32 MMAs.
// Exactly one wait / barrier / commit per iteration (same as R8).
// kv = X @ Wqk^T ; s = K0^T V^T * c ; a = softmax(s) ; q = a @ V ;
// out = perm(q) @ Wd^T + b.     B=4, T=2048, D=2048, H=16.
// ---------------------------------------------------------------------------

#define BM 128
#define BN 128
#define BK 64                        // halves
#define STAGES 3
#define A_BYTES 16384                // 128 rows * 128B
#define B_BYTES 16384
#define STAGE_BYTES (A_BYTES + B_BYTES)
#define SMEM_TOTAL (STAGES * STAGE_BYTES)
#define NTHREADS 128

__device__ __half g_xh [4L * 2048 * 2048];
__device__ __half g_wqk[4096L * 2048];
__device__ __half g_wd [2048L * 2048];
__device__ __half g_kv [4L * 2048 * 4096];
__device__ __half g_k0t[4L * 2048 * 2048];
__device__ __half g_vt [4L * 2048 * 2048];
__device__ __half g_s  [4L * 2048 * 2048];
__device__ __half g_q  [4L * 2048 * 2048];

static __device__ __forceinline__ uint32_t smem_u32(const void* p) {
    uint32_t a;
    asm("{ .reg .u64 t; cvta.to.shared.u64 t, %1; cvt.u32.u64 %0, t; }"
        : "=r"(a) : "l"(p));
    return a;
}
static __device__ __forceinline__ void cp16(uint32_t dst, const void* src) {
    asm volatile("cp.async.cg.shared.global [%0], [%1], 16;\n" :: "r"(dst), "l"(src));
}
static __device__ __forceinline__ void cp_commit() {
    asm volatile("cp.async.commit_group;\n");
}
template<int N> static __device__ __forceinline__ void cp_wait() {
    asm volatile("cp.async.wait_group %0;\n" :: "n"(N));
}
static __device__ __forceinline__ void ldsm4(uint32_t& r0, uint32_t& r1,
                                             uint32_t& r2, uint32_t& r3,
                                             uint32_t addr) {
    asm volatile("ldmatrix.sync.aligned.m8n8.x4.shared.b16 {%0,%1,%2,%3}, [%4];"
                 : "=r"(r0), "=r"(r1), "=r"(r2), "=r"(r3) : "r"(addr));
}
static __device__ __forceinline__ void mma_f16(float c[4], const uint32_t a[4],
                                               const uint32_t b[2]) {
    asm volatile(
        "mma.sync.aligned.m16n8k16.row.col.f32.f16.f16.f32 "
        "{%0,%1,%2,%3}, {%4,%5,%6,%7}, {%8,%9}, {%0,%1,%2,%3};\n"
        : "+f"(c[0]), "+f"(c[1]), "+f"(c[2]), "+f"(c[3])
        : "r"(a[0]), "r"(a[1]), "r"(a[2]), "r"(a[3]), "r"(b[0]), "r"(b[1]));
}

// smem tile rows of 64 halves = 128B = 8 chunks of 16B; chunk ^= row&7.
static __device__ __forceinline__ uint32_t tile_addr(uint32_t base, int row, int k) {
    return base + (uint32_t)(row * 128 + ((((k >> 3) ^ (row & 7))) << 4)
                             + ((k & 7) << 1));
}

// C = alpha * A·B^T (+bias). A:[M,K] K-major half, B:[N,K] K-major half.
template<bool OUTF32, bool BIAS, bool PERMOUT>
__global__ __launch_bounds__(NTHREADS, 2)
void gemm_h(const __half* __restrict__ A, const __half* __restrict__ B,
            void* __restrict__ Cv, const float* __restrict__ bias,
            int K, long sA, long sB, long ldc,
            long bA, long bB, long bC, float alpha)
{
    extern __shared__ __half smem[];
    const uint32_t sbase = smem_u32(smem);

    A += (long)blockIdx.z * bA;
    B += (long)blockIdx.z * bB;

    const int tid  = threadIdx.x;
    const int warp = tid >> 5;
    const int lane = tid & 31;
    const int wm   = warp >> 1;          // 0..1  (64-row slice)
    const int wn   = warp & 1;           // 0..1  (64-col slice)
    const int g    = lane >> 2;          // 0..7
    const int tig  = lane & 3;           // 0..3
    const long rowBase = (long)blockIdx.y * BM;
    const long colBase = (long)blockIdx.x * BN;

    // ldmatrix lane-derived fragment coords
    const int lblk = lane >> 3;
    const int frag_row = ((lblk & 1) << 3) + (lane & 7);
    const int frag_kc  = (lblk >> 1) << 3;

    float acc[4][8][4];
#pragma unroll
    for (int i = 0; i < 4; ++i)
#pragma unroll
        for (int j = 0; j < 8; ++j)
#pragma unroll
            for (int c = 0; c < 4; ++c) acc[i][j][c] = 0.f;

    auto issueTile = [&](int t) {
        const int st = t % STAGES;
        const uint32_t aB = sbase + (uint32_t)st * STAGE_BYTES;
        const uint32_t bB2 = aB + A_BYTES;
        const int k0 = t * BK;
#pragma unroll
        for (int r = 0; r < 8; ++r) {               // A: 128 rows x 8 chunks
            int idx = tid + r * NTHREADS;
            int row = idx >> 3, c = idx & 7;
            cp16(aB + (uint32_t)(row * 128 + ((c ^ (row & 7)) << 4)),
                 A + (rowBase + row) * sA + (k0 + c * 8));
        }
#pragma unroll
        for (int r = 0; r < 8; ++r) {               // B: 128 rows x 8 chunks
            int idx = tid + r * NTHREADS;
            int row = idx >> 3, c = idx & 7;
            cp16(bB2 + (uint32_t)(row * 128 + ((c ^ (row & 7)) << 4)),
                 B + (colBase + row) * sB + (k0 + c * 8));
        }
    };

    auto loadFragsA = [&](uint32_t aB, int ks, uint32_t a[4][4]) {
#pragma unroll
        for (int i = 0; i < 4; ++i) {
            int row = wm * 64 + i * 16 + frag_row;
            ldsm4(a[i][0], a[i][1], a[i][2], a[i][3],
                  tile_addr(aB, row, ks + frag_kc));
        }
    };
    auto loadFragsB = [&](uint32_t bB2, int ks, uint32_t b[8][2]) {
#pragma unroll
        for (int j2 = 0; j2 < 4; ++j2) {
            int nrow = wn * 64 + j2 * 16 + frag_row;
            uint32_t q0, q1, q2, q3;
            ldsm4(q0, q1, q2, q3, tile_addr(bB2, nrow, ks + frag_kc));
            b[2 * j2][0] = q0; b[2 * j2 + 1][0] = q1;
            b[2 * j2][1] = q2; b[2 * j2 + 1][1] = q3;
        }
    };

    uint32_t afr[2][4][4], bfr[2][8][2];
    const int nt = K / BK;

    issueTile(0); cp_commit();
    issueTile(1); cp_commit();
    cp_wait<1>();                    // tile 0 resident (this thread)
    __syncthreads();                 // publish tile 0
    loadFragsA(sbase, 0, afr[0]);
    loadFragsB(sbase + A_BYTES, 0, bfr[0]);

    int cur = 0;
    for (int t = 0; t < nt; ++t) {
        const uint32_t aB = sbase + (uint32_t)(t % STAGES) * STAGE_BYTES;
        const uint32_t bB2 = aB + A_BYTES;
        // slabs 0..2: prefetch next slab's frags, then MMA current
#pragma unroll
        for (int slab = 0; slab < 3; ++slab) {
            const int nxt = cur ^ 1;
            loadFragsA(aB, (slab + 1) * 16, afr[nxt]);
            loadFragsB(bB2, (slab + 1) * 16, bfr[nxt]);
#pragma unroll
            for (int i = 0; i < 4; ++i)
#pragma unroll
                for (int j = 0; j < 8; ++j)
                    mma_f16(acc[i][j], afr[cur][i], bfr[cur][j]);
            cur = nxt;
        }
        // slab 3: all tile-t reads done -> barrier here; hide the
        // post-barrier work (issue t+2, prefetch slab0 of t+1) under MMAs
        cp_wait<0>();                // tile t+1 resident (this thread)
        __syncthreads();             // publish t+1; stage (t+2)%3 reader-free
        if (t + 2 < nt) issueTile(t + 2);
        cp_commit();                 // one group per iter (maybe empty)
        {
            const int nxt = cur ^ 1;
            if (t + 1 < nt) {
                const uint32_t aBn =
                    sbase + (uint32_t)((t + 1) % STAGES) * STAGE_BYTES;
                loadFragsA(aBn, 0, afr[nxt]);
                loadFragsB(aBn + A_BYTES, 0, bfr[nxt]);
            }
#pragma unroll
            for (int i = 0; i < 4; ++i)
#pragma unroll
                for (int j = 0; j < 8; ++j)
                    mma_f16(acc[i][j], afr[cur][i], bfr[cur][j]);
            cur = nxt;
        }
    }

    // ---- epilogue ----
#pragma unroll
    for (int i = 0; i < 4; ++i) {
#pragma unroll
        for (int hh = 0; hh < 2; ++hh) {
            long rloc = rowBase + wm * 64 + i * 16 + g + hh * 8;
            long orow;
            if (PERMOUT) {
                int ii = (int)rloc;          // rowBase spans [0,2048)
                int bb = blockIdx.z;
                orow = (long)((ii & 127) >> 5) * 2048
                     + (long)(((ii & 31) << 6) | (bb << 4) | (ii >> 7));
            } else {
                orow = rloc;
            }
#pragma unroll
            for (int j = 0; j < 8; ++j) {
                long col = colBase + wn * 64 + j * 8 + tig * 2;
                float v0 = acc[i][j][hh * 2]     * alpha;
                float v1 = acc[i][j][hh * 2 + 1] * alpha;
                if (OUTF32) {
                    float* C = (float*)Cv + (long)blockIdx.z * bC;
                    if (BIAS) {
                        const float2 bv = *(const float2*)(bias + col);
                        v0 += bv.x; v1 += bv.y;
                    }
                    *(float2*)(C + orow * ldc + col) = make_float2(v0, v1);
                } else {
                    __half* C = (__half*)Cv + (long)blockIdx.z * bC;
                    *(__half2*)(C + orow * ldc + col) = __floats2half2_rn(v0, v1);
                }
            }
        }
    }
}

// float -> half conversion (4 elems/thread)
__global__ __launch_bounds__(256)
void to_half(const float* __restrict__ in, __half* __restrict__ out, long n4)
{
    long i = (long)blockIdx.x * blockDim.x + threadIdx.x;
    long stride = (long)gridDim.x * blockDim.x;
    for (; i < n4; i += stride) {
        float4 v = ((const float4*)in)[i];
        ((__half2*)out)[2 * i]     = __floats2half2_rn(v.x, v.y);
        ((__half2*)out)[2 * i + 1] = __floats2half2_rn(v.z, v.w);
    }
}

// half 32x32 transpose: dst[b][x][y] = src[b][y][colOff + x]
__global__ __launch_bounds__(256)
void transpose_h(const __half* __restrict__ src, __half* __restrict__ dst,
                 long srcStride, long colOff, long srcBatch, long dstBatch)
{
    __shared__ __half tile[32][33];
    const long sb = (long)blockIdx.z * srcBatch;
    const long db = (long)blockIdx.z * dstBatch;
    const int x0 = blockIdx.x * 32, y0 = blockIdx.y * 32;
    const int tx = threadIdx.x, ty = threadIdx.y;
#pragma unroll
    for (int j = 0; j < 4; ++j)
        tile[ty + j * 8][tx] =
            src[sb + (long)(y0 + ty + j * 8) * srcStride + colOff + x0 + tx];
    __syncthreads();
#pragma unroll
    for (int j = 0; j < 4; ++j)
        dst[db + (long)(x0 + ty + j * 8) * 2048 + y0 + tx] = tile[tx][ty + j * 8];
}

// softmax over half rows of 2048 (fp32 math), in place.
__global__ __launch_bounds__(256)
void softmax2048h(__half* __restrict__ S)
{
    const long row = blockIdx.x;
    __half* p = S + row * 2048;
    const int tid = threadIdx.x, lane = tid & 31, wid = tid >> 5;

    float v[8];
    float m = -1e30f;
#pragma unroll
    for (int j = 0; j < 8; ++j) {
        v[j] = __half2float(p[tid + j * 256]);
        m = fmaxf(m, v[j]);
    }
#pragma unroll
    for (int o = 16; o > 0; o >>= 1)
        m = fmaxf(m, __shfl_xor_sync(0xFFFFFFFFu, m, o));
    __shared__ float red[8];
    if (lane == 0) red[wid] = m;
    __syncthreads();
    float mm = red[0];
#pragma unroll
    for (int w = 1; w < 8; ++w) mm = fmaxf(mm, red[w]);
    __syncthreads();
    float sum = 0.f;
#pragma unroll
    for (int j = 0; j < 8; ++j) { v[j] = expf(v[j] - mm); sum += v[j]; }
#pragma unroll
    for (int o = 16; o > 0; o >>= 1)
        sum += __shfl_xor_sync(0xFFFFFFFFu, sum, o);
    if (lane == 0) red[wid] = sum;
    __syncthreads();
    float tot = 0.f;
#pragma unroll
    for (int w = 0; w < 8; ++w) tot += red[w];
    const float inv = 1.f / tot;
#pragma unroll
    for (int j = 0; j < 8; ++j)
        p[tid + j * 256] = __float2half_rn(v[j] * inv);
}

extern "C" void kernel_launch(void* const* d_in, const int* in_sizes, int n_in,
                              void* d_out, int out_size)
{
    const float* x       = (const float*)d_in[0];
    const float* w_qk    = (const float*)d_in[1];
    const float* w_dense = (const float*)d_in[2];
    const float* b_dense = (const float*)d_in[3];
    float* out = (float*)d_out;

    __half *xh, *wqkh, *wdh, *kv, *k0t, *vt, *s, *q;
    cudaGetSymbolAddress((void**)&xh,   g_xh);
    cudaGetSymbolAddress((void**)&wqkh, g_wqk);
    cudaGetSymbolAddress((void**)&wdh,  g_wd);
    cudaGetSymbolAddress((void**)&kv,   g_kv);
    cudaGetSymbolAddress((void**)&k0t,  g_k0t);
    cudaGetSymbolAddress((void**)&vt,   g_vt);
    cudaGetSymbolAddress((void**)&s,    g_s);
    cudaGetSymbolAddress((void**)&q,    g_q);

    static int attr_done = 0;
    if (!attr_done) {
        cudaFuncSetAttribute(gemm_h<false, false, false>,
                             cudaFuncAttributeMaxDynamicSharedMemorySize, SMEM_TOTAL);
        cudaFuncSetAttribute(gemm_h<false, false, true>,
                             cudaFuncAttributeMaxDynamicSharedMemorySize, SMEM_TOTAL);
        cudaFuncSetAttribute(gemm_h<true,  true,  false>,
                             cudaFuncAttributeMaxDynamicSharedMemorySize, SMEM_TOTAL);
        attr_done = 1;
    }

    const float scale = (float)(1.0 / sqrt((double)2048 * 2047 / 2.0));

    // 0) convert inputs to half
    to_half<<<1024, 256>>>(x,       xh,   (4L * 2048 * 2048) / 4);
    to_half<<<512,  256>>>(w_qk,    wqkh, (4096L * 2048) / 4);
    to_half<<<512,  256>>>(w_dense, wdh,  (2048L * 2048) / 4);

    // 1) kv = X @ Wqk^T : M=8192, N=4096  (half out)
    gemm_h<false, false, false><<<dim3(4096 / BN, 8192 / BM, 1), NTHREADS, SMEM_TOTAL>>>(
        xh, wqkh, kv, nullptr, 2048, 2048, 2048, 4096, 0, 0, 0, 1.f);

    // 1b) k0t[b,i,m] = kv[b,m,i];  vt[b,d,t] = kv[b,t,2048+d]
    transpose_h<<<dim3(64, 64, 4), dim3(32, 8)>>>(kv, k0t, 4096, 0,
                                                  2048L * 4096, 2048L * 2048);
    transpose_h<<<dim3(64, 64, 4), dim3(32, 8)>>>(kv, vt, 4096, 2048,
                                                  2048L * 4096, 2048L * 2048);

    // 2) s[b,i,j] = scale * sum_m k0t[b,i,m] * v[b,j,m]   (half out)
    gemm_h<false, false, false><<<dim3(2048 / BN, 2048 / BM, 4), NTHREADS, SMEM_TOTAL>>>(
        k0t, kv + 2048, s, nullptr, 2048, 2048, 4096, 2048,
        2048L * 2048, 2048L * 4096, 2048L * 2048, scale);

    // 3) a = softmax(s) in-place (half)
    softmax2048h<<<8192, 256>>>(s);

    // 4) qp[perm(b,i), d] = sum_t a[b,i,t] * vt[b,d,t]   (half out, perm rows)
    gemm_h<false, false, true><<<dim3(2048 / BN, 2048 / BM, 4), NTHREADS, SMEM_TOTAL>>>(
        s, vt, q, nullptr, 2048, 2048, 2048, 2048,
        2048L * 2048, 2048L * 2048, 0, 1.f);

    // 5) out = qp @ Wd^T + b : M=8192, N=2048  (float out + bias)
    gemm_h<true, true, false><<<dim3(2048 / BN, 8192 / BM, 1), NTHREADS, SMEM_TOTAL>>>(
        q, wdh, out, b_dense, 2048, 2048, 2048, 2048, 0, 0, 0, 1.f);
}

// round 14
// speedup vs baseline: 1.9942x; 1.0173x over previous
#include <cuda_runtime.h>
#include <cuda_fp16.h>
#include <math.h>
#include <stdint.h>

// ---------------------------------------------------------------------------
// SelfAttention — round 13: R12 GEMM core (fp16 mma.sync, 128x128x64, 4 warps,
// 64x64 warp tiles, rotated mainloop, 3-stage cp.async, 2 CTAs/SM) with:
//  * GEMM1 computes kvT = Wqk @ X^T  -> k0^T and v^T layouts come for free;
//    only ONE transpose left (v -> [j,m])
//  * softmax loads/stores vectorized as __half2
// kv = X @ Wqk^T ; s = K0^T V^T * c ; a = softmax(s) ; q = a @ V ;
// out = perm(q) @ Wd^T + b.     B=4, T=2048, D=2048, H=16.
// ---------------------------------------------------------------------------

#define BM 128
#define BN 128
#define BK 64                        // halves
#define STAGES 3
#define A_BYTES 16384                // 128 rows * 128B
#define B_BYTES 16384
#define STAGE_BYTES (A_BYTES + B_BYTES)
#define SMEM_TOTAL (STAGES * STAGE_BYTES)
#define NTHREADS 128

__device__ __half g_xh [4L * 2048 * 2048];
__device__ __half g_wqk[4096L * 2048];
__device__ __half g_wd [2048L * 2048];
__device__ __half g_kv [4096L * 8192];      // kvT: [e(4096)][b*2048+t]
__device__ __half g_vjm[4L * 2048 * 2048];  // v[b][j][m]
__device__ __half g_s  [4L * 2048 * 2048];
__device__ __half g_q  [4L * 2048 * 2048];

static __device__ __forceinline__ uint32_t smem_u32(const void* p) {
    uint32_t a;
    asm("{ .reg .u64 t; cvta.to.shared.u64 t, %1; cvt.u32.u64 %0, t; }"
        : "=r"(a) : "l"(p));
    return a;
}
static __device__ __forceinline__ void cp16(uint32_t dst, const void* src) {
    asm volatile("cp.async.cg.shared.global [%0], [%1], 16;\n" :: "r"(dst), "l"(src));
}
static __device__ __forceinline__ void cp_commit() {
    asm volatile("cp.async.commit_group;\n");
}
template<int N> static __device__ __forceinline__ void cp_wait() {
    asm volatile("cp.async.wait_group %0;\n" :: "n"(N));
}
static __device__ __forceinline__ void ldsm4(uint32_t& r0, uint32_t& r1,
                                             uint32_t& r2, uint32_t& r3,
                                             uint32_t addr) {
    asm volatile("ldmatrix.sync.aligned.m8n8.x4.shared.b16 {%0,%1,%2,%3}, [%4];"
                 : "=r"(r0), "=r"(r1), "=r"(r2), "=r"(r3) : "r"(addr));
}
static __device__ __forceinline__ void mma_f16(float c[4], const uint32_t a[4],
                                               const uint32_t b[2]) {
    asm volatile(
        "mma.sync.aligned.m16n8k16.row.col.f32.f16.f16.f32 "
        "{%0,%1,%2,%3}, {%4,%5,%6,%7}, {%8,%9}, {%0,%1,%2,%3};\n"
        : "+f"(c[0]), "+f"(c[1]), "+f"(c[2]), "+f"(c[3])
        : "r"(a[0]), "r"(a[1]), "r"(a[2]), "r"(a[3]), "r"(b[0]), "r"(b[1]));
}

// smem tile rows of 64 halves = 128B = 8 chunks of 16B; chunk ^= row&7.
static __device__ __forceinline__ uint32_t tile_addr(uint32_t base, int row, int k) {
    return base + (uint32_t)(row * 128 + ((((k >> 3) ^ (row & 7))) << 4)
                             + ((k & 7) << 1));
}

// C = alpha * A·B^T (+bias). A:[M,K] K-major half, B:[N,K] K-major half.
template<bool OUTF32, bool BIAS, bool PERMOUT>
__global__ __launch_bounds__(NTHREADS, 2)
void gemm_h(const __half* __restrict__ A, const __half* __restrict__ B,
            void* __restrict__ Cv, const float* __restrict__ bias,
            int K, long sA, long sB, long ldc,
            long bA, long bB, long bC, float alpha)
{
    extern __shared__ __half smem[];
    const uint32_t sbase = smem_u32(smem);

    A += (long)blockIdx.z * bA;
    B += (long)blockIdx.z * bB;

    const int tid  = threadIdx.x;
    const int warp = tid >> 5;
    const int lane = tid & 31;
    const int wm   = warp >> 1;          // 0..1  (64-row slice)
    const int wn   = warp & 1;           // 0..1  (64-col slice)
    const int g    = lane >> 2;          // 0..7
    const int tig  = lane & 3;           // 0..3
    const long rowBase = (long)blockIdx.y * BM;
    const long colBase = (long)blockIdx.x * BN;

    // ldmatrix lane-derived fragment coords
    const int lblk = lane >> 3;
    const int frag_row = ((lblk & 1) << 3) + (lane & 7);
    const int frag_kc  = (lblk >> 1) << 3;

    float acc[4][8][4];
#pragma unroll
    for (int i = 0; i < 4; ++i)
#pragma unroll
        for (int j = 0; j < 8; ++j)
#pragma unroll
            for (int c = 0; c < 4; ++c) acc[i][j][c] = 0.f;

    auto issueTile = [&](int t) {
        const int st = t % STAGES;
        const uint32_t aB = sbase + (uint32_t)st * STAGE_BYTES;
        const uint32_t bB2 = aB + A_BYTES;
        const int k0 = t * BK;
#pragma unroll
        for (int r = 0; r < 8; ++r) {               // A: 128 rows x 8 chunks
            int idx = tid + r * NTHREADS;
            int row = idx >> 3, c = idx & 7;
            cp16(aB + (uint32_t)(row * 128 + ((c ^ (row & 7)) << 4)),
                 A + (rowBase + row) * sA + (k0 + c * 8));
        }
#pragma unroll
        for (int r = 0; r < 8; ++r) {               // B: 128 rows x 8 chunks
            int idx = tid + r * NTHREADS;
            int row = idx >> 3, c = idx & 7;
            cp16(bB2 + (uint32_t)(row * 128 + ((c ^ (row & 7)) << 4)),
                 B + (colBase + row) * sB + (k0 + c * 8));
        }
    };

    auto loadFragsA = [&](uint32_t aB, int ks, uint32_t a[4][4]) {
#pragma unroll
        for (int i = 0; i < 4; ++i) {
            int row = wm * 64 + i * 16 + frag_row;
            ldsm4(a[i][0], a[i][1], a[i][2], a[i][3],
                  tile_addr(aB, row, ks + frag_kc));
        }
    };
    auto loadFragsB = [&](uint32_t bB2, int ks, uint32_t b[8][2]) {
#pragma unroll
        for (int j2 = 0; j2 < 4; ++j2) {
            int nrow = wn * 64 + j2 * 16 + frag_row;
            uint32_t q0, q1, q2, q3;
            ldsm4(q0, q1, q2, q3, tile_addr(bB2, nrow, ks + frag_kc));
            b[2 * j2][0] = q0; b[2 * j2 + 1][0] = q1;
            b[2 * j2][1] = q2; b[2 * j2 + 1][1] = q3;
        }
    };

    uint32_t afr[2][4][4], bfr[2][8][2];
    const int nt = K / BK;

    issueTile(0); cp_commit();
    issueTile(1); cp_commit();
    cp_wait<1>();                    // tile 0 resident (this thread)
    __syncthreads();                 // publish tile 0
    loadFragsA(sbase, 0, afr[0]);
    loadFragsB(sbase + A_BYTES, 0, bfr[0]);

    int cur = 0;
    for (int t = 0; t < nt; ++t) {
        const uint32_t aB = sbase + (uint32_t)(t % STAGES) * STAGE_BYTES;
        const uint32_t bB2 = aB + A_BYTES;
        // slabs 0..2: prefetch next slab's frags, then MMA current
#pragma unroll
        for (int slab = 0; slab < 3; ++slab) {
            const int nxt = cur ^ 1;
            loadFragsA(aB, (slab + 1) * 16, afr[nxt]);
            loadFragsB(bB2, (slab + 1) * 16, bfr[nxt]);
#pragma unroll
            for (int i = 0; i < 4; ++i)
#pragma unroll
                for (int j = 0; j < 8; ++j)
                    mma_f16(acc[i][j], afr[cur][i], bfr[cur][j]);
            cur = nxt;
        }
        // slab 3: all tile-t reads done -> barrier here; hide the
        // post-barrier work (issue t+2, prefetch slab0 of t+1) under MMAs
        cp_wait<0>();                // tile t+1 resident (this thread)
        __syncthreads();             // publish t+1; stage (t+2)%3 reader-free
        if (t + 2 < nt) issueTile(t + 2);
        cp_commit();                 // one group per iter (maybe empty)
        {
            const int nxt = cur ^ 1;
            if (t + 1 < nt) {
                const uint32_t aBn =
                    sbase + (uint32_t)((t + 1) % STAGES) * STAGE_BYTES;
                loadFragsA(aBn, 0, afr[nxt]);
                loadFragsB(aBn + A_BYTES, 0, bfr[nxt]);
            }
#pragma unroll
            for (int i = 0; i < 4; ++i)
#pragma unroll
                for (int j = 0; j < 8; ++j)
                    mma_f16(acc[i][j], afr[cur][i], bfr[cur][j]);
            cur = nxt;
        }
    }

    // ---- epilogue ----
#pragma unroll
    for (int i = 0; i < 4; ++i) {
#pragma unroll
        for (int hh = 0; hh < 2; ++hh) {
            long rloc = rowBase + wm * 64 + i * 16 + g + hh * 8;
            long orow;
            if (PERMOUT) {
                int ii = (int)rloc;          // rowBase spans [0,2048)
                int bb = blockIdx.z;
                orow = (long)((ii & 127) >> 5) * 2048
                     + (long)(((ii & 31) << 6) | (bb << 4) | (ii >> 7));
            } else {
                orow = rloc;
            }
#pragma unroll
            for (int j = 0; j < 8; ++j) {
                long col = colBase + wn * 64 + j * 8 + tig * 2;
                float v0 = acc[i][j][hh * 2]     * alpha;
                float v1 = acc[i][j][hh * 2 + 1] * alpha;
                if (OUTF32) {
                    float* C = (float*)Cv + (long)blockIdx.z * bC;
                    if (BIAS) {
                        const float2 bv = *(const float2*)(bias + col);
                        v0 += bv.x; v1 += bv.y;
                    }
                    *(float2*)(C + orow * ldc + col) = make_float2(v0, v1);
                } else {
                    __half* C = (__half*)Cv + (long)blockIdx.z * bC;
                    *(__half2*)(C + orow * ldc + col) = __floats2half2_rn(v0, v1);
                }
            }
        }
    }
}

// float -> half conversion (4 elems/thread)
__global__ __launch_bounds__(256)
void to_half(const float* __restrict__ in, __half* __restrict__ out, long n4)
{
    long i = (long)blockIdx.x * blockDim.x + threadIdx.x;
    long stride = (long)gridDim.x * blockDim.x;
    for (; i < n4; i += stride) {
        float4 v = ((const float4*)in)[i];
        ((__half2*)out)[2 * i]     = __floats2half2_rn(v.x, v.y);
        ((__half2*)out)[2 * i + 1] = __floats2half2_rn(v.z, v.w);
    }
}

// half 32x32 transpose: dst[b][x][y] = src[y*srcStride + colOff + x + b*srcBatch]
__global__ __launch_bounds__(256)
void transpose_h(const __half* __restrict__ src, __half* __restrict__ dst,
                 long srcStride, long colOff, long srcBatch, long dstBatch)
{
    __shared__ __half tile[32][33];
    const long sb = (long)blockIdx.z * srcBatch;
    const long db = (long)blockIdx.z * dstBatch;
    const int x0 = blockIdx.x * 32, y0 = blockIdx.y * 32;
    const int tx = threadIdx.x, ty = threadIdx.y;
#pragma unroll
    for (int j = 0; j < 4; ++j)
        tile[ty + j * 8][tx] =
            src[sb + (long)(y0 + ty + j * 8) * srcStride + colOff + x0 + tx];
    __syncthreads();
#pragma unroll
    for (int j = 0; j < 4; ++j)
        dst[db + (long)(x0 + ty + j * 8) * 2048 + y0 + tx] = tile[tx][ty + j * 8];
}

// softmax over half rows of 2048 (fp32 math), vectorized half2 I/O, in place.
__global__ __launch_bounds__(256)
void softmax2048h(__half* __restrict__ S)
{
    const long row = blockIdx.x;
    __half2* p = (__half2*)(S + row * 2048);
    const int tid = threadIdx.x, lane = tid & 31, wid = tid >> 5;

    float v[8];
    float m = -1e30f;
#pragma unroll
    for (int j = 0; j < 4; ++j) {
        float2 f = __half22float2(p[tid + j * 256]);
        v[2 * j] = f.x; v[2 * j + 1] = f.y;
        m = fmaxf(m, fmaxf(f.x, f.y));
    }
#pragma unroll
    for (int o = 16; o > 0; o >>= 1)
        m = fmaxf(m, __shfl_xor_sync(0xFFFFFFFFu, m, o));
    __shared__ float red[8];
    if (lane == 0) red[wid] = m;
    __syncthreads();
    float mm = red[0];
#pragma unroll
    for (int w = 1; w < 8; ++w) mm = fmaxf(mm, red[w]);
    __syncthreads();
    float sum = 0.f;
#pragma unroll
    for (int j = 0; j < 8; ++j) { v[j] = expf(v[j] - mm); sum += v[j]; }
#pragma unroll
    for (int o = 16; o > 0; o >>= 1)
        sum += __shfl_xor_sync(0xFFFFFFFFu, sum, o);
    if (lane == 0) red[wid] = sum;
    __syncthreads();
    float tot = 0.f;
#pragma unroll
    for (int w = 0; w < 8; ++w) tot += red[w];
    const float inv = 1.f / tot;
#pragma unroll
    for (int j = 0; j < 4; ++j)
        p[tid + j * 256] = __floats2half2_rn(v[2 * j] * inv, v[2 * j + 1] * inv);
}

extern "C" void kernel_launch(void* const* d_in, const int* in_sizes, int n_in,
                              void* d_out, int out_size)
{
    const float* x       = (const float*)d_in[0];
    const float* w_qk    = (const float*)d_in[1];
    const float* w_dense = (const float*)d_in[2];
    const float* b_dense = (const float*)d_in[3];
    float* out = (float*)d_out;

    __half *xh, *wqkh, *wdh, *kvT, *vjm, *s, *q;
    cudaGetSymbolAddress((void**)&xh,   g_xh);
    cudaGetSymbolAddress((void**)&wqkh, g_wqk);
    cudaGetSymbolAddress((void**)&wdh,  g_wd);
    cudaGetSymbolAddress((void**)&kvT,  g_kv);
    cudaGetSymbolAddress((void**)&vjm,  g_vjm);
    cudaGetSymbolAddress((void**)&s,    g_s);
    cudaGetSymbolAddress((void**)&q,    g_q);

    static int attr_done = 0;
    if (!attr_done) {
        cudaFuncSetAttribute(gemm_h<false, false, false>,
                             cudaFuncAttributeMaxDynamicSharedMemorySize, SMEM_TOTAL);
        cudaFuncSetAttribute(gemm_h<false, false, true>,
                             cudaFuncAttributeMaxDynamicSharedMemorySize, SMEM_TOTAL);
        cudaFuncSetAttribute(gemm_h<true,  true,  false>,
                             cudaFuncAttributeMaxDynamicSharedMemorySize, SMEM_TOTAL);
        attr_done = 1;
    }

    const float scale = (float)(1.0 / sqrt((double)2048 * 2047 / 2.0));

    // 0) convert inputs to half
    to_half<<<1024, 256>>>(x,       xh,   (4L * 2048 * 2048) / 4);
    to_half<<<512,  256>>>(w_qk,    wqkh, (4096L * 2048) / 4);
    to_half<<<512,  256>>>(w_dense, wdh,  (2048L * 2048) / 4);

    // 1) kvT = Wqk @ X^T : M=4096 (e), N=8192 (b*2048+t), ldc=8192
    gemm_h<false, false, false><<<dim3(8192 / BN, 4096 / BM, 1), NTHREADS, SMEM_TOTAL>>>(
        wqkh, xh, kvT, nullptr, 2048, 2048, 2048, 8192, 0, 0, 0, 1.f);

    // 1b) vjm[b][j][m] = kvT[2048+m][b*2048+j]  (single transpose)
    transpose_h<<<dim3(64, 64, 4), dim3(32, 8)>>>(kvT, vjm, 8192, 2048L * 8192,
                                                  2048, 2048L * 2048);

    // 2) s[b][i][j] = scale * sum_m kvT[i][b*2048+m] * vjm[b][j][m]
    gemm_h<false, false, false><<<dim3(2048 / BN, 2048 / BM, 4), NTHREADS, SMEM_TOTAL>>>(
        kvT, vjm, s, nullptr, 2048, 8192, 2048, 2048,
        2048, 2048L * 2048, 2048L * 2048, scale);

    // 3) a = softmax(s) in-place (half)
    softmax2048h<<<8192, 256>>>(s);

    // 4) qp[perm(b,i), d] = sum_t a[b][i][t] * kvT[2048+d][b*2048+t]
    gemm_h<false, false, true><<<dim3(2048 / BN, 2048 / BM, 4), NTHREADS, SMEM_TOTAL>>>(
        s, kvT + 2048L * 8192, q, nullptr, 2048, 2048, 8192, 2048,
        2048L * 2048, 2048, 0, 1.f);

    // 5) out = qp @ Wd^T + b : M=8192, N=2048  (float out + bias)
    gemm_h<true, true, false><<<dim3(2048 / BN, 8192 / BM, 1), NTHREADS, SMEM_TOTAL>>>(
        q, wdh, out, b_dense, 2048, 2048, 2048, 2048, 0, 0, 0, 1.f);
}

// round 17
// speedup vs baseline: 2.0112x; 1.0085x over previous
#include <cuda_runtime.h>
#include <cuda_fp16.h>
#include <math.h>
#include <stdint.h>

// ---------------------------------------------------------------------------
// SelfAttention — round 16 (= R15 resubmit; infra failure last round):
// R13 GEMM core untouched (fp16 mma.sync, 128x128x64, 4 warps, 64x64 warp
// tiles, rotated mainloop, 3-stage cp.async, 2 CTAs/SM; kvT layout, single
// transpose). Aux:
//  * one fused to_half launch for x / w_qk / w_dense
//  * softmax: R13's proven 1-row-per-block shape + __expf
// kv = X @ Wqk^T ; s = K0^T V^T * c ; a = softmax(s) ; q = a @ V ;
// out = perm(q) @ Wd^T + b.     B=4, T=2048, D=2048, H=16.
// ---------------------------------------------------------------------------

#define BM 128
#define BN 128
#define BK 64                        // halves
#define STAGES 3
#define A_BYTES 16384                // 128 rows * 128B
#define B_BYTES 16384
#define STAGE_BYTES (A_BYTES + B_BYTES)
#define SMEM_TOTAL (STAGES * STAGE_BYTES)
#define NTHREADS 128

__device__ __half g_xh [4L * 2048 * 2048];
__device__ __half g_wqk[4096L * 2048];
__device__ __half g_wd [2048L * 2048];
__device__ __half g_kv [4096L * 8192];      // kvT: [e(4096)][b*2048+t]
__device__ __half g_vjm[4L * 2048 * 2048];  // v[b][j][m]
__device__ __half g_s  [4L * 2048 * 2048];
__device__ __half g_q  [4L * 2048 * 2048];

static __device__ __forceinline__ uint32_t smem_u32(const void* p) {
    uint32_t a;
    asm("{ .reg .u64 t; cvta.to.shared.u64 t, %1; cvt.u32.u64 %0, t; }"
        : "=r"(a) : "l"(p));
    return a;
}
static __device__ __forceinline__ void cp16(uint32_t dst, const void* src) {
    asm volatile("cp.async.cg.shared.global [%0], [%1], 16;\n" :: "r"(dst), "l"(src));
}
static __device__ __forceinline__ void cp_commit() {
    asm volatile("cp.async.commit_group;\n");
}
template<int N> static __device__ __forceinline__ void cp_wait() {
    asm volatile("cp.async.wait_group %0;\n" :: "n"(N));
}
static __device__ __forceinline__ void ldsm4(uint32_t& r0, uint32_t& r1,
                                             uint32_t& r2, uint32_t& r3,
                                             uint32_t addr) {
    asm volatile("ldmatrix.sync.aligned.m8n8.x4.shared.b16 {%0,%1,%2,%3}, [%4];"
                 : "=r"(r0), "=r"(r1), "=r"(r2), "=r"(r3) : "r"(addr));
}
static __device__ __forceinline__ void mma_f16(float c[4], const uint32_t a[4],
                                               const uint32_t b[2]) {
    asm volatile(
        "mma.sync.aligned.m16n8k16.row.col.f32.f16.f16.f32 "
        "{%0,%1,%2,%3}, {%4,%5,%6,%7}, {%8,%9}, {%0,%1,%2,%3};\n"
        : "+f"(c[0]), "+f"(c[1]), "+f"(c[2]), "+f"(c[3])
        : "r"(a[0]), "r"(a[1]), "r"(a[2]), "r"(a[3]), "r"(b[0]), "r"(b[1]));
}

// smem tile rows of 64 halves = 128B = 8 chunks of 16B; chunk ^= row&7.
static __device__ __forceinline__ uint32_t tile_addr(uint32_t base, int row, int k) {
    return base + (uint32_t)(row * 128 + ((((k >> 3) ^ (row & 7))) << 4)
                             + ((k & 7) << 1));
}

// C = alpha * A·B^T (+bias). A:[M,K] K-major half, B:[N,K] K-major half.
template<bool OUTF32, bool BIAS, bool PERMOUT>
__global__ __launch_bounds__(NTHREADS, 2)
void gemm_h(const __half* __restrict__ A, const __half* __restrict__ B,
            void* __restrict__ Cv, const float* __restrict__ bias,
            int K, long sA, long sB, long ldc,
            long bA, long bB, long bC, float alpha)
{
    extern __shared__ __half smem[];
    const uint32_t sbase = smem_u32(smem);

    A += (long)blockIdx.z * bA;
    B += (long)blockIdx.z * bB;

    const int tid  = threadIdx.x;
    const int warp = tid >> 5;
    const int lane = tid & 31;
    const int wm   = warp >> 1;          // 0..1  (64-row slice)
    const int wn   = warp & 1;           // 0..1  (64-col slice)
    const int g    = lane >> 2;          // 0..7
    const int tig  = lane & 3;           // 0..3
    const long rowBase = (long)blockIdx.y * BM;
    const long colBase = (long)blockIdx.x * BN;

    // ldmatrix lane-derived fragment coords
    const int lblk = lane >> 3;
    const int frag_row = ((lblk & 1) << 3) + (lane & 7);
    const int frag_kc  = (lblk >> 1) << 3;

    float acc[4][8][4];
#pragma unroll
    for (int i = 0; i < 4; ++i)
#pragma unroll
        for (int j = 0; j < 8; ++j)
#pragma unroll
            for (int c = 0; c < 4; ++c) acc[i][j][c] = 0.f;

    auto issueTile = [&](int t) {
        const int st = t % STAGES;
        const uint32_t aB = sbase + (uint32_t)st * STAGE_BYTES;
        const uint32_t bB2 = aB + A_BYTES;
        const int k0 = t * BK;
#pragma unroll
        for (int r = 0; r < 8; ++r) {               // A: 128 rows x 8 chunks
            int idx = tid + r * NTHREADS;
            int row = idx >> 3, c = idx & 7;
            cp16(aB + (uint32_t)(row * 128 + ((c ^ (row & 7)) << 4)),
                 A + (rowBase + row) * sA + (k0 + c * 8));
        }
#pragma unroll
        for (int r = 0; r < 8; ++r) {               // B: 128 rows x 8 chunks
            int idx = tid + r * NTHREADS;
            int row = idx >> 3, c = idx & 7;
            cp16(bB2 + (uint32_t)(row * 128 + ((c ^ (row & 7)) << 4)),
                 B + (colBase + row) * sB + (k0 + c * 8));
        }
    };

    auto loadFragsA = [&](uint32_t aB, int ks, uint32_t a[4][4]) {
#pragma unroll
        for (int i = 0; i < 4; ++i) {
            int row = wm * 64 + i * 16 + frag_row;
            ldsm4(a[i][0], a[i][1], a[i][2], a[i][3],
                  tile_addr(aB, row, ks + frag_kc));
        }
    };
    auto loadFragsB = [&](uint32_t bB2, int ks, uint32_t b[8][2]) {
#pragma unroll
        for (int j2 = 0; j2 < 4; ++j2) {
            int nrow = wn * 64 + j2 * 16 + frag_row;
            uint32_t q0, q1, q2, q3;
            ldsm4(q0, q1, q2, q3, tile_addr(bB2, nrow, ks + frag_kc));
            b[2 * j2][0] = q0; b[2 * j2 + 1][0] = q1;
            b[2 * j2][1] = q2; b[2 * j2 + 1][1] = q3;
        }
    };

    uint32_t afr[2][4][4], bfr[2][8][2];
    const int nt = K / BK;

    issueTile(0); cp_commit();
    issueTile(1); cp_commit();
    cp_wait<1>();                    // tile 0 resident (this thread)
    __syncthreads();                 // publish tile 0
    loadFragsA(sbase, 0, afr[0]);
    loadFragsB(sbase + A_BYTES, 0, bfr[0]);

    int cur = 0;
    for (int t = 0; t < nt; ++t) {
        const uint32_t aB = sbase + (uint32_t)(t % STAGES) * STAGE_BYTES;
        const uint32_t bB2 = aB + A_BYTES;
        // slabs 0..2: prefetch next slab's frags, then MMA current
#pragma unroll
        for (int slab = 0; slab < 3; ++slab) {
            const int nxt = cur ^ 1;
            loadFragsA(aB, (slab + 1) * 16, afr[nxt]);
            loadFragsB(bB2, (slab + 1) * 16, bfr[nxt]);
#pragma unroll
            for (int i = 0; i < 4; ++i)
#pragma unroll
                for (int j = 0; j < 8; ++j)
                    mma_f16(acc[i][j], afr[cur][i], bfr[cur][j]);
            cur = nxt;
        }
        // slab 3: all tile-t reads done -> barrier here; hide the
        // post-barrier work (issue t+2, prefetch slab0 of t+1) under MMAs
        cp_wait<0>();                // tile t+1 resident (this thread)
        __syncthreads();             // publish t+1; stage (t+2)%3 reader-free
        if (t + 2 < nt) issueTile(t + 2);
        cp_commit();                 // one group per iter (maybe empty)
        {
            const int nxt = cur ^ 1;
            if (t + 1 < nt) {
                const uint32_t aBn =
                    sbase + (uint32_t)((t + 1) % STAGES) * STAGE_BYTES;
                loadFragsA(aBn, 0, afr[nxt]);
                loadFragsB(aBn + A_BYTES, 0, bfr[nxt]);
            }
#pragma unroll
            for (int i = 0; i < 4; ++i)
#pragma unroll
                for (int j = 0; j < 8; ++j)
                    mma_f16(acc[i][j], afr[cur][i], bfr[cur][j]);
            cur = nxt;
        }
    }

    // ---- epilogue ----
#pragma unroll
    for (int i = 0; i < 4; ++i) {
#pragma unroll
        for (int hh = 0; hh < 2; ++hh) {
            long rloc = rowBase + wm * 64 + i * 16 + g + hh * 8;
            long orow;
            if (PERMOUT) {
                int ii = (int)rloc;          // rowBase spans [0,2048)
                int bb = blockIdx.z;
                orow = (long)((ii & 127) >> 5) * 2048
                     + (long)(((ii & 31) << 6) | (bb << 4) | (ii >> 7));
            } else {
                orow = rloc;
            }
#pragma unroll
            for (int j = 0; j < 8; ++j) {
                long col = colBase + wn * 64 + j * 8 + tig * 2;
                float v0 = acc[i][j][hh * 2]     * alpha;
                float v1 = acc[i][j][hh * 2 + 1] * alpha;
                if (OUTF32) {
                    float* C = (float*)Cv + (long)blockIdx.z * bC;
                    if (BIAS) {
                        const float2 bv = *(const float2*)(bias + col);
                        v0 += bv.x; v1 += bv.y;
                    }
                    *(float2*)(C + orow * ldc + col) = make_float2(v0, v1);
                } else {
                    __half* C = (__half*)Cv + (long)blockIdx.z * bC;
                    *(__half2*)(C + orow * ldc + col) = __floats2half2_rn(v0, v1);
                }
            }
        }
    }
}

// fused float -> half conversion for three tensors (grid-stride, float4)
__global__ __launch_bounds__(256)
void to_half3(const float* __restrict__ a, __half* __restrict__ oa, long na4,
              const float* __restrict__ b, __half* __restrict__ ob, long nb4,
              const float* __restrict__ c, __half* __restrict__ oc, long nc4)
{
    const long total = na4 + nb4 + nc4;
    long i = (long)blockIdx.x * blockDim.x + threadIdx.x;
    const long stride = (long)gridDim.x * blockDim.x;
    for (; i < total; i += stride) {
        const float* src; __half* dst; long k;
        if (i < na4)            { src = a; dst = oa; k = i; }
        else if (i < na4 + nb4) { src = b; dst = ob; k = i - na4; }
        else                    { src = c; dst = oc; k = i - na4 - nb4; }
        float4 v = ((const float4*)src)[k];
        ((__half2*)dst)[2 * k]     = __floats2half2_rn(v.x, v.y);
        ((__half2*)dst)[2 * k + 1] = __floats2half2_rn(v.z, v.w);
    }
}

// half 32x32 transpose: dst[b][x][y] = src[y*srcStride + colOff + x + b*srcBatch]
__global__ __launch_bounds__(256)
void transpose_h(const __half* __restrict__ src, __half* __restrict__ dst,
                 long srcStride, long colOff, long srcBatch, long dstBatch)
{
    __shared__ __half tile[32][33];
    const long sb = (long)blockIdx.z * srcBatch;
    const long db = (long)blockIdx.z * dstBatch;
    const int x0 = blockIdx.x * 32, y0 = blockIdx.y * 32;
    const int tx = threadIdx.x, ty = threadIdx.y;
#pragma unroll
    for (int j = 0; j < 4; ++j)
        tile[ty + j * 8][tx] =
            src[sb + (long)(y0 + ty + j * 8) * srcStride + colOff + x0 + tx];
    __syncthreads();
#pragma unroll
    for (int j = 0; j < 4; ++j)
        dst[db + (long)(x0 + ty + j * 8) * 2048 + y0 + tx] = tile[tx][ty + j * 8];
}

// softmax over half rows of 2048 (fp32 math, __expf), half2 I/O,
// ONE row per 256-thread block (proven R13 shape: 256 thr x 4 half2 = 1024).
__global__ __launch_bounds__(256)
void softmax2048h(__half* __restrict__ S)
{
    const long row = blockIdx.x;
    __half2* p = (__half2*)(S + row * 2048);
    const int tid = threadIdx.x, lane = tid & 31, wid = tid >> 5;

    float v[8];
    float m = -1e30f;
#pragma unroll
    for (int j = 0; j < 4; ++j) {
        float2 f = __half22float2(p[tid + j * 256]);
        v[2 * j] = f.x; v[2 * j + 1] = f.y;
        m = fmaxf(m, fmaxf(f.x, f.y));
    }
#pragma unroll
    for (int o = 16; o > 0; o >>= 1)
        m = fmaxf(m, __shfl_xor_sync(0xFFFFFFFFu, m, o));
    __shared__ float red[8];
    if (lane == 0) red[wid] = m;
    __syncthreads();
    float mm = red[0];
#pragma unroll
    for (int w = 1; w < 8; ++w) mm = fmaxf(mm, red[w]);
    __syncthreads();
    float sum = 0.f;
#pragma unroll
    for (int j = 0; j < 8; ++j) { v[j] = __expf(v[j] - mm); sum += v[j]; }
#pragma unroll
    for (int o = 16; o > 0; o >>= 1)
        sum += __shfl_xor_sync(0xFFFFFFFFu, sum, o);
    if (lane == 0) red[wid] = sum;
    __syncthreads();
    float tot = 0.f;
#pragma unroll
    for (int w = 0; w < 8; ++w) tot += red[w];
    const float inv = 1.f / tot;
#pragma unroll
    for (int j = 0; j < 4; ++j)
        p[tid + j * 256] = __floats2half2_rn(v[2 * j] * inv, v[2 * j + 1] * inv);
}

extern "C" void kernel_launch(void* const* d_in, const int* in_sizes, int n_in,
                              void* d_out, int out_size)
{
    const float* x       = (const float*)d_in[0];
    const float* w_qk    = (const float*)d_in[1];
    const float* w_dense = (const float*)d_in[2];
    const float* b_dense = (const float*)d_in[3];
    float* out = (float*)d_out;

    __half *xh, *wqkh, *wdh, *kvT, *vjm, *s, *q;
    cudaGetSymbolAddress((void**)&xh,   g_xh);
    cudaGetSymbolAddress((void**)&wqkh, g_wqk);
    cudaGetSymbolAddress((void**)&wdh,  g_wd);
    cudaGetSymbolAddress((void**)&kvT,  g_kv);
    cudaGetSymbolAddress((void**)&vjm,  g_vjm);
    cudaGetSymbolAddress((void**)&s,    g_s);
    cudaGetSymbolAddress((void**)&q,    g_q);

    static int attr_done = 0;
    if (!attr_done) {
        cudaFuncSetAttribute(gemm_h<false, false, false>,
                             cudaFuncAttributeMaxDynamicSharedMemorySize, SMEM_TOTAL);
        cudaFuncSetAttribute(gemm_h<false, false, true>,
                             cudaFuncAttributeMaxDynamicSharedMemorySize, SMEM_TOTAL);
        cudaFuncSetAttribute(gemm_h<true,  true,  false>,
                             cudaFuncAttributeMaxDynamicSharedMemorySize, SMEM_TOTAL);
        attr_done = 1;
    }

    const float scale = (float)(1.0 / sqrt((double)2048 * 2047 / 2.0));

    // 0) convert all inputs to half in one launch
    to_half3<<<2048, 256>>>(x,       xh,   (4L * 2048 * 2048) / 4,
                            w_qk,    wqkh, (4096L * 2048) / 4,
                            w_dense, wdh,  (2048L * 2048) / 4);

    // 1) kvT = Wqk @ X^T : M=4096 (e), N=8192 (b*2048+t), ldc=8192
    gemm_h<false, false, false><<<dim3(8192 / BN, 4096 / BM, 1), NTHREADS, SMEM_TOTAL>>>(
        wqkh, xh, kvT, nullptr, 2048, 2048, 2048, 8192, 0, 0, 0, 1.f);

    // 1b) vjm[b][j][m] = kvT[2048+m][b*2048+j]  (single transpose)
    transpose_h<<<dim3(64, 64, 4), dim3(32, 8)>>>(kvT, vjm, 8192, 2048L * 8192,
                                                  2048, 2048L * 2048);

    // 2) s[b][i][j] = scale * sum_m kvT[i][b*2048+m] * vjm[b][j][m]
    gemm_h<false, false, false><<<dim3(2048 / BN, 2048 / BM, 4), NTHREADS, SMEM_TOTAL>>>(
        kvT, vjm, s, nullptr, 2048, 8192, 2048, 2048,
        2048, 2048L * 2048, 2048L * 2048, scale);

    // 3) a = softmax(s) in-place (half), one row per block
    softmax2048h<<<8192, 256>>>(s);

    // 4) qp[perm(b,i), d] = sum_t a[b][i][t] * kvT[2048+d][b*2048+t]
    gemm_h<false, false, true><<<dim3(2048 / BN, 2048 / BM, 4), NTHREADS, SMEM_TOTAL>>>(
        s, kvT + 2048L * 8192, q, nullptr, 2048, 2048, 8192, 2048,
        2048L * 2048, 2048, 0, 1.f);

    // 5) out = qp @ Wd^T + b : M=8192, N=2048  (float out + bias)
    gemm_h<true, true, false><<<dim3(2048 / BN, 8192 / BM, 1), NTHREADS, SMEM_TOTAL>>>(
        q, wdh, out, b_dense, 2048, 2048, 2048, 2048, 0, 0, 0, 1.f);
}